// round 7
// baseline (speedup 1.0000x reference)
#include <cuda_runtime.h>
#include <math.h>
#include <stdint.h>

#define TT 1024
#define HH 512

// ---- persistent state (device globals; no allocation allowed) ----
__device__ float g_h[2][64 * 512];   // double-buffered h exchange [parity][batch][k]
__device__ int   g_flag[16][8];      // per-group per-CTA step flags (reset each launch)

// ---------------- packed f32x2 helpers ----------------
__device__ __forceinline__ unsigned long long pack2(float x, float y) {
    unsigned long long r;
    asm("mov.b64 %0, {%1, %2};" : "=l"(r) : "f"(x), "f"(y));
    return r;
}
__device__ __forceinline__ unsigned long long fma2(unsigned long long a,
                                                   unsigned long long b,
                                                   unsigned long long c) {
    unsigned long long d;
    asm("fma.rn.f32x2 %0, %1, %2, %3;" : "=l"(d) : "l"(a), "l"(b), "l"(c));
    return d;
}
__device__ __forceinline__ float2 unpack2(unsigned long long v) {
    float2 r;
    asm("mov.b64 {%0, %1}, %2;" : "=f"(r.x), "=f"(r.y) : "l"(v));
    return r;
}

// ===================== Phase 1: xw = x @ W[0:512] + b  -> out =====================
// M=65536, N=512, K=512. BM=128, BN=64, BK=16, 256 threads, 8x4 per thread.
__global__ void __launch_bounds__(256) gemm_xw_kernel(
    const float* __restrict__ x, const float* __restrict__ Wg,
    const float* __restrict__ bias, float* __restrict__ C)
{
    // block (0,0) resets phase-2 flags (phase 2 launches after us in stream order)
    if (blockIdx.x == 0 && blockIdx.y == 0 && threadIdx.x < 128)
        ((int*)g_flag)[threadIdx.x] = 0;

    __shared__ float As[16][132];
    __shared__ float Bs[16][68];

    const int tid = threadIdx.x;
    const int tn  = tid & 15;
    const int tm  = tid >> 4;
    const int m0  = blockIdx.x * 128;
    const int n0  = blockIdx.y * 64;

    unsigned long long acc[8][2];
#pragma unroll
    for (int i = 0; i < 8; i++) { acc[i][0] = 0ull; acc[i][1] = 0ull; }

    for (int k0 = 0; k0 < 512; k0 += 16) {
#pragma unroll
        for (int i = tid; i < 512; i += 256) {
            int m = i >> 2, kq = i & 3;
            float4 v = *(const float4*)(x + (size_t)(m0 + m) * 512 + k0 + kq * 4);
            As[kq * 4 + 0][m] = v.x;
            As[kq * 4 + 1][m] = v.y;
            As[kq * 4 + 2][m] = v.z;
            As[kq * 4 + 3][m] = v.w;
        }
        {
            int kk = tid >> 4, nq = tid & 15;
            float4 v = *(const float4*)(Wg + (size_t)(k0 + kk) * 512 + n0 + nq * 4);
            *(float4*)&Bs[kk][nq * 4] = v;
        }
        __syncthreads();
#pragma unroll
        for (int kk = 0; kk < 16; kk++) {
            ulonglong2 bb = *(const ulonglong2*)&Bs[kk][tn * 4];
#pragma unroll
            for (int i = 0; i < 8; i++) {
                float a = As[kk][tm * 8 + i];
                unsigned long long ap = pack2(a, a);
                acc[i][0] = fma2(ap, bb.x, acc[i][0]);
                acc[i][1] = fma2(ap, bb.y, acc[i][1]);
            }
        }
        __syncthreads();
    }

    float b0 = bias[n0 + tn * 4 + 0];
    float b1 = bias[n0 + tn * 4 + 1];
    float b2 = bias[n0 + tn * 4 + 2];
    float b3 = bias[n0 + tn * 4 + 3];
#pragma unroll
    for (int i = 0; i < 8; i++) {
        int m = m0 + tm * 8 + i;
        float2 p0 = unpack2(acc[i][0]);
        float2 p1 = unpack2(acc[i][1]);
        float4 o;
        o.x = p0.x + b0; o.y = p0.y + b1; o.z = p1.x + b2; o.w = p1.y + b3;
        *(float4*)(C + (size_t)m * 512 + n0 + tn * 4) = o;
    }
}

// ===================== Phase 2: sequential recurrence ==============================
// 16 groups x 8 CTAs (128 persistent). Group g: batches 4g..4g+3. CTA c: cols 64c..64c+63.
// 512 threads: thread (kc, col) handles K-chunk kc (64 k's) x 1 column x 4 batches.
// Wh in registers as k-pairs (32 u64/thread). h in SMEM; broadcast LDS.128 yields
// {h_k,h_{k+1}} u64 pairs directly -> zero packing in the hot loop.
// Step barrier: per-CTA release flags in one 32B L2 sector, 8 parallel acquire-polls.
__global__ void __launch_bounds__(512, 1) recurrent_kernel(
    const float* __restrict__ Wg, float* __restrict__ out)
{
    __shared__ __align__(16) float hbuf[2][4][512];  // [parity][batch][k]
    __shared__ float red[8][256];                    // [kc][batch*64+col]

    const int tid  = threadIdx.x;
    const int g    = blockIdx.x >> 3;     // group 0..15
    const int c    = blockIdx.x & 7;      // col-slice 0..7
    const int kc   = tid >> 6;            // K-chunk 0..7 (k in [64kc, 64kc+64))
    const int colw = tid & 63;            // this thread's column within slice

    // ---- Wh slice into registers as k-pairs: w[k2] = {Wh[kc*64+2k2][col], [2k2+1][col]} ----
    unsigned long long w[32];
    {
        const float* wb = Wg + (size_t)(512 + kc * 64) * 512 + c * 64 + colw;
#pragma unroll
        for (int k2 = 0; k2 < 32; k2++)
            w[k2] = pack2(wb[(size_t)(2 * k2) * 512], wb[(size_t)(2 * k2 + 1) * 512]);
    }
    // ---- h_{-1} = 0 ----
    for (int i = tid; i < 2 * 4 * 512 / 4; i += 512)
        ((float4*)hbuf)[i] = make_float4(0.f, 0.f, 0.f, 0.f);
    __syncthreads();

    // epilogue mapping (threads 0..255 only)
    const int bo  = (tid >> 6) & 3;
    const int col = tid & 63;
    float* outrow = out + (size_t)(g * 4 + bo) * TT * HH + c * 64 + col;
    const int hoff = (g * 4 + bo) * 512 + c * 64 + col;
    int* myflag  = &g_flag[g][c];
    int* pollflag = &g_flag[g][tid & 7];

    for (int t = 0; t < TT; t++) {
        float xwv = (tid < 256) ? outrow[(size_t)t * HH] : 0.0f;  // early LDG

        const int p = t & 1;
        const ulonglong2* h0 = (const ulonglong2*)&hbuf[p][0][kc * 64];
        const ulonglong2* h1 = (const ulonglong2*)&hbuf[p][1][kc * 64];
        const ulonglong2* h2 = (const ulonglong2*)&hbuf[p][2][kc * 64];
        const ulonglong2* h3 = (const ulonglong2*)&hbuf[p][3][kc * 64];

        unsigned long long a0 = 0, a1 = 0, a2 = 0, a3 = 0;  // per-batch {even-k, odd-k}
#pragma unroll
        for (int i = 0; i < 16; i++) {        // 4 k's per iteration
            ulonglong2 q0 = h0[i];            // broadcast: all lanes same addr
            ulonglong2 q1 = h1[i];
            ulonglong2 q2 = h2[i];
            ulonglong2 q3 = h3[i];
            unsigned long long wa = w[2 * i], wb2 = w[2 * i + 1];
            a0 = fma2(q0.x, wa, a0);
            a1 = fma2(q1.x, wa, a1);
            a2 = fma2(q2.x, wa, a2);
            a3 = fma2(q3.x, wa, a3);
            a0 = fma2(q0.y, wb2, a0);
            a1 = fma2(q1.y, wb2, a1);
            a2 = fma2(q2.y, wb2, a2);
            a3 = fma2(q3.y, wb2, a3);
        }
        {
            float2 f0 = unpack2(a0), f1 = unpack2(a1);
            float2 f2 = unpack2(a2), f3 = unpack2(a3);
            red[kc][0 * 64 + colw] = f0.x + f0.y;
            red[kc][1 * 64 + colw] = f1.x + f1.y;
            red[kc][2 * 64 + colw] = f2.x + f2.y;
            red[kc][3 * 64 + colw] = f3.x + f3.y;
        }
        __syncthreads();

        // epilogue: threads 0..255, one (batch, col) each
        if (tid < 256) {
            float z = xwv;
#pragma unroll
            for (int k2 = 0; k2 < 8; k2++) z += red[k2][tid];
            float hv = tanhf(z);
            outrow[(size_t)t * HH] = hv;                       // this IS the output
            if (t + 1 < TT) __stcg(&g_h[(t + 1) & 1][hoff], hv);
        }

        if (t + 1 < TT) {
            __syncthreads();   // h stores issued by all epilogue threads; red reusable
            if (tid == 0)
                asm volatile("st.release.gpu.global.s32 [%0], %1;"
                             :: "l"(myflag), "r"(t + 1) : "memory");
            if (tid < 8) {     // 8 lanes poll 8 flags (one 32B sector -> 1 coalesced LDG)
                int v;
                do {
                    asm volatile("ld.acquire.gpu.global.s32 %0, [%1];"
                                 : "=r"(v) : "l"(pollflag) : "memory");
                } while (v <= t);
            }
            __syncthreads();
            // coherent reload of group's h into next parity buffer (1 float4/thread)
            const float4* src = (const float4*)&g_h[(t + 1) & 1][g * 2048];
            ((float4*)hbuf[(t + 1) & 1])[tid] = __ldcg(src + tid);
            __syncthreads();
        }
    }
}

// ======================================================================================
extern "C" void kernel_launch(void* const* d_in, const int* in_sizes, int n_in,
                              void* d_out, int out_size) {
    (void)in_sizes; (void)n_in; (void)out_size;
    const float* x  = (const float*)d_in[0];   // [64,1024,512]
    const float* Wg = (const float*)d_in[1];   // [1024,512]
    const float* bb = (const float*)d_in[2];   // [512]
    float* out = (float*)d_out;                // [64,1024,512]

    gemm_xw_kernel<<<dim3(512, 8), 256>>>(x, Wg, bb, out);
    recurrent_kernel<<<128, 512>>>(Wg, out);
}